// round 5
// baseline (speedup 1.0000x reference)
#include <cuda_runtime.h>

#define B_  16
#define C_  8
#define H_  512
#define W_  512
#define TW  32           // tile width
#define TH  16           // tile height
#define HW_ 34           // TW + 2 (halo)
#define HH_ 18           // TH + 2 (halo)
#define SROW 35          // padded row (float2 elements)
#define NTHREADS 256
#define SMEM_BYTES (C_ * HH_ * SROW * (int)sizeof(float2))   // 40320 < 48KB

__device__ double g_acc;

__global__ void k_zero() { g_acc = 0.0; }

__global__ void k_final(float* out) { out[0] = (float)(-g_acc); }

__global__ __launch_bounds__(NTHREADS)
void k_main(const float* __restrict__ cmap,
            const float* __restrict__ target,
            const float* __restrict__ con) {
    extern __shared__ float2 s[];   // [C_][HH_][SROW] : (p, log p)

    const int w0 = blockIdx.x * TW;
    const int h0 = blockIdx.y * TH;
    const int b  = blockIdx.z;
    const int tid = threadIdx.x;

    // ---- load phase: sigmoid + log-sigmoid computed ONCE per element ------
    const float* cb = cmap + (size_t)b * C_ * H_ * W_;
    for (int i = tid; i < C_ * HH_ * HW_; i += NTHREADS) {
        int c   = i / (HH_ * HW_);
        int rem = i - c * (HH_ * HW_);
        int hy  = rem / HW_;
        int wx  = rem - hy * HW_;
        int gh = h0 - 1 + hy;
        int gw = w0 - 1 + wx;
        float p, lp;
        if ((unsigned)gh < H_ && (unsigned)gw < W_) {
            float x  = cb[((size_t)c * H_ + gh) * W_ + gw];
            float e  = __expf(-fabsf(x));           // EX2
            float op = 1.0f + e;
            float l  = __logf(op);                   // LG2  (= log1p(e), e<=1)
            float r  = __fdividef(1.0f, op);         // RCP
            p  = (x >= 0.0f) ? r : e * r;            // sigmoid(x)
            lp = fminf(x, 0.0f) - l;                 // log sigmoid(x)
        } else {
            p = 0.0f; lp = -1e9f;                    // zero padding outside image
        }
        s[(c * HH_ + hy) * SROW + wx] = make_float2(p, lp);
    }
    __syncthreads();

    // vote channel k pairs center channel k with channel 7-k at neighbor k
    // (raster-order 8-neighborhood)
    const int DH[8] = {-1, -1, -1,  0, 0,  1, 1, 1};
    const int DW[8] = {-1,  0,  1, -1, 1, -1, 0, 1};

    float acc = 0.0f;
    const int px = tid & 31;
    const int ty = tid >> 5;   // 0..7

    #pragma unroll
    for (int q = 0; q < 2; q++) {
        const int py = ty + q * 8;
        const int gh = h0 + py;
        const int gw = w0 + px;

        float pc[8], lpc[8], tc[8];
        float sum_t = 0.0f;
        #pragma unroll
        for (int c = 0; c < 8; c++) {
            float2 v = s[(c * HH_ + (py + 1)) * SROW + (px + 1)];
            pc[c]  = v.x;
            lpc[c] = v.y;
            size_t gi = ((size_t)(b * C_ + c) * H_ + gh) * W_ + gw;
            tc[c] = con[gi];                         // con_target (cold read)
            sum_t += tc[c];
        }

        // conmap BCE (weight 0.8): log(1-p) = log p - x  (exact identity)
        #pragma unroll
        for (int c = 0; c < 8; c++) {
            size_t gi = ((size_t)(b * C_ + c) * H_ + gh) * W_ + gw;
            float x   = cmap[gi];                    // L1 hit (loaded above)
            float lp  = fmaxf(lpc[c], -100.0f);
            float lmp = fmaxf(lpc[c] - x, -100.0f);
            acc += 0.8f * ((tc[c] != 0.0f) ? lp : lmp);
        }

        // votes / bimap BCE (weight 0.2)
        float vmin = 1e30f, vsum = 0.0f;
        #pragma unroll
        for (int k = 0; k < 8; k++) {
            float2 nb = s[((7 - k) * HH_ + (py + 1 + DH[k])) * SROW
                          + (px + 1 + DW[k])];
            float v    = pc[k] * nb.x;
            float lv   = fmaxf(lpc[k] + nb.y, -100.0f);      // log(pa*pb), free
            float omv  = fmaf(-pc[k], nb.x, 1.0f);           // 1 - v, single round
            float l1mv = fmaxf(__logf(omv), -100.0f);
            acc += 0.2f * ((tc[k] != 0.0f) ? lv : l1mv);
            vmin = fminf(vmin, v);
            vsum += v;
        }

        // decouple / de loss (weight 1.0)
        bool edge  = (sum_t > 0.0f) && (sum_t < 8.0f);
        float glo  = vsum * 0.125f;
        float da   = edge ? (1.0f - vmin) : glo;      // d
        float db   = edge ? vmin : (1.0f - glo);      // 1 - d (exact per-branch)
        float logd   = fmaxf(__logf(da), -100.0f);
        float log1md = fmaxf(__logf(db), -100.0f);
        float tt = target[((size_t)b * H_ + gh) * W_ + gw];
        acc += (tt != 0.0f) ? logd : log1md;
    }

    // ---------------- reduction ----------------
    #pragma unroll
    for (int off = 16; off; off >>= 1)
        acc += __shfl_xor_sync(0xFFFFFFFFu, acc, off);

    __shared__ float warpsum[8];
    if ((tid & 31) == 0) warpsum[tid >> 5] = acc;
    __syncthreads();
    if (tid < 8) {
        float v = warpsum[tid];
        #pragma unroll
        for (int off = 4; off; off >>= 1)
            v += __shfl_xor_sync(0xFFu, v, off);
        if (tid == 0) atomicAdd(&g_acc, (double)v);
    }
}

extern "C" void kernel_launch(void* const* d_in, const int* in_sizes, int n_in,
                              void* d_out, int out_size) {
    const float* cmap   = (const float*)d_in[0];
    const float* target = (const float*)d_in[1];
    const float* con    = (const float*)d_in[2];

    k_zero<<<1, 1>>>();
    dim3 grid(W_ / TW, H_ / TH, B_);
    k_main<<<grid, NTHREADS, SMEM_BYTES>>>(cmap, target, con);
    k_final<<<1, 1>>>((float*)d_out);
}